// round 1
// baseline (speedup 1.0000x reference)
#include <cuda_runtime.h>
#include <cstdint>

// Packed fp32x2 add (Blackwell sm_100a+): one SASS instruction for 2 fp32 adds.
#define ADD_F32X2(out, a, b) \
    asm("add.rn.f32x2 %0, %1, %2;" : "=l"(out) : "l"(a), "l"(b))

constexpr int S = 512, H = 8, D = 64;
constexpr int TILE = 64;
constexpr int STR = 66;  // padded smem row stride in floats (keeps 8B alignment, kills bank conflicts)

__global__ __launch_bounds__(256, 2)
void l1attn_kernel(const float* __restrict__ q, const float* __restrict__ k,
                   float* __restrict__ out) {
    __shared__ __align__(16) float qs[TILE * STR];
    __shared__ __align__(16) float ks[TILE * STR];

    const int bh = blockIdx.z;          // b*H + h
    const int b  = bh >> 3;
    const int h  = bh & 7;
    const int i0 = blockIdx.x * TILE;   // q-position tile (output columns)
    const int j0 = blockIdx.y * TILE;   // k-position tile (output rows)
    const int tid = threadIdx.x;

    // ---- Fill smem tiles: q[i0..i0+63][0..63], and NEGATED k[j0..j0+63][0..63] ----
    // 64 rows x 32 float2 per tile. Global rows are 64 contiguous floats (256B), coalesced.
    #pragma unroll
    for (int idx = tid; idx < TILE * (D / 2); idx += 256) {
        const int r  = idx >> 5;        // row within tile
        const int dv = idx & 31;        // float2 index along d
        const float2 qv = *reinterpret_cast<const float2*>(
            q + (((b * S + i0 + r) * H + h) * D) + 2 * dv);
        *reinterpret_cast<float2*>(qs + r * STR + 2 * dv) = qv;

        float2 kv = *reinterpret_cast<const float2*>(
            k + (((b * S + j0 + r) * H + h) * D) + 2 * dv);
        kv.x = -kv.x; kv.y = -kv.y;     // pre-negate: inner loop uses packed ADD as SUB
        *reinterpret_cast<float2*>(ks + r * STR + 2 * dv) = kv;
    }
    __syncthreads();

    const int tx = tid & 15;            // i direction (16 lanes)
    const int ty = tid >> 4;            // j direction

    // 4x4 register block, each accumulator is a packed f32x2 (two d-halves summed at the end).
    unsigned long long acc[4][4];
    #pragma unroll
    for (int c = 0; c < 4; ++c)
        #pragma unroll
        for (int e = 0; e < 4; ++e) acc[c][e] = 0ull;

    #pragma unroll 4
    for (int d2 = 0; d2 < D / 2; ++d2) {
        unsigned long long q2[4], k2[4];
        // i rows interleaved by 16 -> LDS.64 across the 16 tx lanes hits 16 distinct
        // bank-pairs (stride 66 floats: bank = 2*tx mod 32) => conflict-free.
        #pragma unroll
        for (int c = 0; c < 4; ++c)
            q2[c] = *reinterpret_cast<const unsigned long long*>(
                qs + (tx + 16 * c) * STR + 2 * d2);
        // k rows: only 2 distinct ty per warp -> broadcast, conflict-free.
        #pragma unroll
        for (int e = 0; e < 4; ++e)
            k2[e] = *reinterpret_cast<const unsigned long long*>(
                ks + (ty + 16 * e) * STR + 2 * d2);

        #pragma unroll
        for (int c = 0; c < 4; ++c)
            #pragma unroll
            for (int e = 0; e < 4; ++e) {
                unsigned long long dif;
                ADD_F32X2(dif, q2[c], k2[e]);        // q - k   (fma pipe, packed)
                dif &= 0x7FFFFFFF7FFFFFFFull;        // |.| x2  (alu pipe, 2x LOP3)
                unsigned long long t;
                ADD_F32X2(t, acc[c][e], dif);        // acc +=  (fma pipe, packed)
                acc[c][e] = t;
            }
    }

    // ---- Writeback: out[bh][j][i] = -0.125 * (lo + hi) ----
    #pragma unroll
    for (int e = 0; e < 4; ++e) {
        const int j = j0 + ty + 16 * e;
        float* orow = out + ((size_t)bh * S + j) * S + i0;
        #pragma unroll
        for (int c = 0; c < 4; ++c) {
            const unsigned long long a = acc[c][e];
            const float lo = __uint_as_float((unsigned)(a & 0xFFFFFFFFu));
            const float hi = __uint_as_float((unsigned)(a >> 32));
            orow[tx + 16 * c] = -0.125f * (lo + hi);
        }
    }
}

extern "C" void kernel_launch(void* const* d_in, const int* in_sizes, int n_in,
                              void* d_out, int out_size) {
    const float* q = (const float*)d_in[0];
    const float* k = (const float*)d_in[1];
    float* out     = (float*)d_out;
    dim3 grid(S / TILE, S / TILE, 2 * H);   // (i-tiles, j-tiles, B*H)
    l1attn_kernel<<<grid, 256>>>(q, k, out);
}

// round 2
// speedup vs baseline: 1.0655x; 1.0655x over previous
#include <cuda_runtime.h>
#include <cstdint>

// Packed fp32x2 add (sm_100a): one SASS instruction for 2 fp32 adds.
#define ADD_F32X2(out, a, b) \
    asm("add.rn.f32x2 %0, %1, %2;" : "=l"(out) : "l"(a), "l"(b))

constexpr int S = 512, H = 8, D = 64;
constexpr int TILE = 64;
constexpr int STR = 68;  // floats; 272B rows: 16B-aligned (LDS.128 legal) and
                         // bank start = 4*tx mod 32 -> 16 lanes cover all banks, conflict-free.

__global__ __launch_bounds__(256, 3)
void l1attn_kernel(const float* __restrict__ q, const float* __restrict__ k,
                   float* __restrict__ out) {
    __shared__ __align__(16) float qs[TILE * STR];
    __shared__ __align__(16) float ks[TILE * STR];

    const int bh = blockIdx.z;          // b*H + h
    const int b  = bh >> 3;
    const int h  = bh & 7;
    const int i0 = blockIdx.x * TILE;   // q-position tile (output columns)
    const int j0 = blockIdx.y * TILE;   // k-position tile (output rows)
    const int tid = threadIdx.x;

    // ---- Fill smem: q tile and NEGATED k tile (inner loop uses packed ADD as SUB) ----
    #pragma unroll
    for (int idx = tid; idx < TILE * (D / 2); idx += 256) {
        const int r  = idx >> 5;        // row within tile
        const int dv = idx & 31;        // float2 index along d
        const float2 qv = *reinterpret_cast<const float2*>(
            q + (((b * S + i0 + r) * H + h) * D) + 2 * dv);
        *reinterpret_cast<float2*>(qs + r * STR + 2 * dv) = qv;

        float2 kv = *reinterpret_cast<const float2*>(
            k + (((b * S + j0 + r) * H + h) * D) + 2 * dv);
        kv.x = -kv.x; kv.y = -kv.y;
        *reinterpret_cast<float2*>(ks + r * STR + 2 * dv) = kv;
    }
    __syncthreads();

    const int tx = tid & 15;            // i direction (16 lanes)
    const int ty = tid >> 4;            // j direction

    // 4x4 output block per thread; each accumulator is a packed f32x2
    // (both 16B-lane halves fold into the same accumulator).
    unsigned long long acc[4][4];
    #pragma unroll
    for (int c = 0; c < 4; ++c)
        #pragma unroll
        for (int e = 0; e < 4; ++e) acc[c][e] = 0ull;

    // 16 iterations over d in chunks of 4 floats (LDS.128).
    #pragma unroll 8
    for (int d4 = 0; d4 < D / 4; ++d4) {
        ulonglong2 q4[4], k4[4];
        #pragma unroll
        for (int c = 0; c < 4; ++c)
            q4[c] = *reinterpret_cast<const ulonglong2*>(
                qs + (tx + 16 * c) * STR + 4 * d4);
        #pragma unroll
        for (int e = 0; e < 4; ++e)
            k4[e] = *reinterpret_cast<const ulonglong2*>(
                ks + (ty + 16 * e) * STR + 4 * d4);

        #pragma unroll
        for (int c = 0; c < 4; ++c)
            #pragma unroll
            for (int e = 0; e < 4; ++e) {
                unsigned long long d0, d1, t;
                ADD_F32X2(d0, q4[c].x, k4[e].x);      // q - k (2 terms, fma pipe)
                d0 &= 0x7FFFFFFF7FFFFFFFull;          // |.|   (2x LOP3, alu pipe)
                ADD_F32X2(t, acc[c][e], d0);
                acc[c][e] = t;
                ADD_F32X2(d1, q4[c].y, k4[e].y);      // next 2 terms
                d1 &= 0x7FFFFFFF7FFFFFFFull;
                ADD_F32X2(t, acc[c][e], d1);
                acc[c][e] = t;
            }
    }

    // ---- Writeback: out[bh][j][i] = -0.125 * (lo + hi) ----
    #pragma unroll
    for (int e = 0; e < 4; ++e) {
        const int j = j0 + ty + 16 * e;
        float* orow = out + ((size_t)bh * S + j) * S + i0;
        #pragma unroll
        for (int c = 0; c < 4; ++c) {
            const unsigned long long a = acc[c][e];
            const float lo = __uint_as_float((unsigned)(a & 0xFFFFFFFFu));
            const float hi = __uint_as_float((unsigned)(a >> 32));
            orow[tx + 16 * c] = -0.125f * (lo + hi);
        }
    }
}

extern "C" void kernel_launch(void* const* d_in, const int* in_sizes, int n_in,
                              void* d_out, int out_size) {
    const float* q = (const float*)d_in[0];
    const float* k = (const float*)d_in[1];
    float* out     = (float*)d_out;
    dim3 grid(S / TILE, S / TILE, 2 * H);   // (i-tiles, j-tiles, B*H)
    l1attn_kernel<<<grid, 256>>>(q, k, out);
}